// round 6
// baseline (speedup 1.0000x reference)
#include <cuda_runtime.h>
#include <cstdint>

// F=32, B=8192, D=64
// inputs: [F, B, 1, D] fp32 ; output: [B, D*D] fp32
// out[b, i*64+j] = s[b,i] * s[b,j], s = sum_f inputs[f,b,0,:]
//
// Residency strategy (graph-replay steady state):
//   - OUTPUT (134MB, rewritten every replay) -> evict_last: lines stay dirty
//     in L2; rewrites are L2 write-hits and never reach DRAM.
//   - INPUT (64MB, read every replay) -> evict_first streaming loads.
// Per-replay DRAM traffic drops from ~142MB (writes) to ~64MB reads + L2
// overflow churn.

#define F_DIM 32
#define B_DIM 8192
#define D_DIM 64
#define FB_STRIDE ((size_t)B_DIM * D_DIM)   // elements per field slab

__device__ __forceinline__ uint64_t make_evict_last_policy() {
    uint64_t pol;
    asm("createpolicy.fractional.L2::evict_last.b64 %0, 1.0;" : "=l"(pol));
    return pol;
}

__device__ __forceinline__ void stg_v4_hint(float4* p, float4 v, uint64_t pol) {
    asm volatile(
        "st.global.L2::cache_hint.v4.f32 [%0], {%1, %2, %3, %4}, %5;"
        :: "l"(p), "f"(v.x), "f"(v.y), "f"(v.z), "f"(v.w), "l"(pol)
        : "memory");
}

__global__ __launch_bounds__(256, 8)
void opnn_kernel(const float* __restrict__ in, float* __restrict__ out) {
    const int b   = blockIdx.x;
    const int tid = threadIdx.x;      // 256 threads
    const int d   = tid & 63;         // 0..63
    const int g   = tid >> 6;         // 0..3 (field group of 8)

    __shared__ float partial[4][64];
    __shared__ float s[64];

    const uint64_t pol = make_evict_last_policy();

    // Field-sum: each thread sums 8 fields for one d. Per-field access is a
    // contiguous 256B line across d (coalesced); 8 independent loads -> MLP.
    // .cs: input is the streaming/evict-first party.
    const float* base = in + (size_t)b * D_DIM + d + (size_t)(g * 8) * FB_STRIDE;
    float acc = 0.f;
#pragma unroll
    for (int k = 0; k < 8; k++)
        acc += __ldcs(base + (size_t)k * FB_STRIDE);
    partial[g][d] = acc;
    __syncthreads();

    if (g == 0) {
        s[d] = partial[0][d] + partial[1][d] + partial[2][d] + partial[3][d];
    }
    __syncthreads();

    // Outer product: 64x64 = 4096 floats = 1024 float4 stores, coalesced.
    // evict_last hint: keep output lines resident+dirty in L2 so next
    // replay's rewrite is an L2 write-hit (no DRAM round-trip).
    float4* o4 = reinterpret_cast<float4*>(out + (size_t)b * (D_DIM * D_DIM));
    const float4* s4 = reinterpret_cast<const float4*>(s);

#pragma unroll
    for (int r = 0; r < 4; r++) {
        const int idx = tid + r * 256;   // float4 index 0..1023
        const int i   = idx >> 4;        // output row (16 float4 per row)
        const int jc  = idx & 15;        // column chunk
        const float  si = s[i];
        const float4 v  = s4[jc];
        float4 w;
        w.x = si * v.x;
        w.y = si * v.y;
        w.z = si * v.z;
        w.w = si * v.w;
        stg_v4_hint(o4 + idx, w, pol);
    }
}

extern "C" void kernel_launch(void* const* d_in, const int* in_sizes, int n_in,
                              void* d_out, int out_size) {
    const float* in = (const float*)d_in[0];
    float* out = (float*)d_out;
    opnn_kernel<<<B_DIM, 256>>>(in, out);
}

// round 7
// speedup vs baseline: 1.0009x; 1.0009x over previous
#include <cuda_runtime.h>
#include <cstdint>

// F=32, B=8192, D=64
// inputs: [F, B, 1, D] fp32 ; output: [B, D*D] fp32
// out[b, i*64+j] = s[b,i] * s[b,j], s = sum_f inputs[f,b,0,:]
//
// Steady-state model (graph replay): input (64MB) already L2-hits; kernel is
// a ~pure 134MB write stream at the ~4.7TB/s DRAM write ceiling.
// Lever: make a FRACTION (0.7 -> ~94MB < 126MB L2, stable) of output lines
// sticky (evict_last). Sticky lines stay dirty-resident across replays; the
// next replay's store is an L2 write-hit and never costs DRAM. Full pinning
// (f=1.0, 134MB) thrashed; headroom is the fix.

#define F_DIM 32
#define B_DIM 8192
#define D_DIM 64
#define FB_STRIDE ((size_t)B_DIM * D_DIM)   // elements per field slab

__device__ __forceinline__ uint64_t make_policy_f70() {
    uint64_t pol;
    asm("createpolicy.fractional.L2::evict_last.b64 %0, 0.7;" : "=l"(pol));
    return pol;
}

__device__ __forceinline__ void stg_v4_hint(float4* p, float4 v, uint64_t pol) {
    asm volatile(
        "st.global.L2::cache_hint.v4.f32 [%0], {%1, %2, %3, %4}, %5;"
        :: "l"(p), "f"(v.x), "f"(v.y), "f"(v.z), "f"(v.w), "l"(pol)
        : "memory");
}

__global__ __launch_bounds__(256, 8)
void opnn_kernel(const float* __restrict__ in, float* __restrict__ out) {
    const int b   = blockIdx.x;
    const int tid = threadIdx.x;      // 256 threads
    const int d   = tid & 63;         // 0..63
    const int g   = tid >> 6;         // 0..3 (field group of 8)

    __shared__ float partial[4][64];
    __shared__ float s[64];

    const uint64_t pol = make_policy_f70();

    // Field-sum: each thread sums 8 fields for one d. Per-field access is a
    // contiguous 256B line across d (coalesced); 8 independent loads -> MLP.
    // Default load policy: input may use whatever L2 the sticky pool leaves.
    const float* base = in + (size_t)b * D_DIM + d + (size_t)(g * 8) * FB_STRIDE;
    float acc = 0.f;
#pragma unroll
    for (int k = 0; k < 8; k++)
        acc += __ldg(base + (size_t)k * FB_STRIDE);
    partial[g][d] = acc;
    __syncthreads();

    if (g == 0) {
        s[d] = partial[0][d] + partial[1][d] + partial[2][d] + partial[3][d];
    }
    __syncthreads();

    // Outer product: 64x64 = 4096 floats = 1024 float4 stores, coalesced.
    // 70% of lines sticky in L2 across replays -> write-hits, no DRAM cost.
    float4* o4 = reinterpret_cast<float4*>(out + (size_t)b * (D_DIM * D_DIM));
    const float4* s4 = reinterpret_cast<const float4*>(s);

#pragma unroll
    for (int r = 0; r < 4; r++) {
        const int idx = tid + r * 256;   // float4 index 0..1023
        const int i   = idx >> 4;        // output row (16 float4 per row)
        const int jc  = idx & 15;        // column chunk
        const float  si = s[i];
        const float4 v  = s4[jc];
        float4 w;
        w.x = si * v.x;
        w.y = si * v.y;
        w.z = si * v.z;
        w.w = si * v.w;
        stg_v4_hint(o4 + idx, w, pol);
    }
}

extern "C" void kernel_launch(void* const* d_in, const int* in_sizes, int n_in,
                              void* d_out, int out_size) {
    const float* in = (const float*)d_in[0];
    float* out = (float*)d_out;
    opnn_kernel<<<B_DIM, 256>>>(in, out);
}